// round 5
// baseline (speedup 1.0000x reference)
#include <cuda_runtime.h>
#include <cstdint>
#include <cstddef>

#define IMG_B   64
#define IMG_H   32
#define IMG_W   4096
#define NSLICE  512
#define MTOT    32768
#define KTOT    1024
#define NTOT    512

#define GI_MAX  4120            // gi = s*8 + c  in [0, 4120)
#define FSTR    4128            // row stride (floats) of F/EL/ER maps

// Scratch (static device arrays; no runtime allocation).
__device__ float g_F [(size_t)IMG_B * IMG_H * FSTR];   // full conv + bias (pre-ReLU)
__device__ float g_EL[(size_t)IMG_B * IMG_H * FSTR];   // left-edge correction
__device__ float g_ER[(size_t)IMG_B * IMG_H * FSTR];   // right-edge correction
__device__ float g_W [(size_t)NTOT * KTOT];            // W^T tf32-rounded, N x K

// ---------------------------------------------------------------------------
// helpers
// ---------------------------------------------------------------------------
__device__ __forceinline__ float to_tf32(float x) {
    float r;
    asm("cvt.rna.tf32.f32 %0, %1;" : "=f"(r) : "f"(x));
    return r;
}

__device__ __forceinline__ uint32_t smem_u32(const void* p) {
    uint32_t a;
    asm("{ .reg .u64 t; cvta.to.shared.u64 t, %1; cvt.u32.u64 %0, t; }" : "=r"(a) : "l"(p));
    return a;
}

__device__ __forceinline__ void cpa16(uint32_t smem_addr, const void* gptr) {
    asm volatile("cp.async.cg.shared.global [%0], [%1], 16;" :: "r"(smem_addr), "l"(gptr));
}
__device__ __forceinline__ void cpa_commit() {
    asm volatile("cp.async.commit_group;" ::: "memory");
}

__device__ __forceinline__ void ldsm_x4(uint32_t r[4], uint32_t addr) {
    asm volatile("ldmatrix.sync.aligned.m8n8.x4.shared.b16 {%0,%1,%2,%3}, [%4];"
                 : "=r"(r[0]), "=r"(r[1]), "=r"(r[2]), "=r"(r[3]) : "r"(addr));
}

// ---------------------------------------------------------------------------
// Kernel 1: full-image conv maps.
//   P[h][g] = img value for g in [0,4096); 1.0 outside (horizontal pad);
//             rows outside [0,32) are zero (vertical conv pad).
//   F [gi] = bias + sum_{r,j} w[r][j] * P[h+r-1][g+j-1],  gi = g+12
//   EL[gi] = sum_r w[r][0] * P[h+r-1][g-1]
//   ER[gi] = sum_r w[r][2] * P[h+r-1][g+1]
// Strip smem index pi = g' + 13  ->  F uses PS[gi..gi+2], EL PS[gi], ER PS[gi+2].
// Block = (hblk of 4 rows, b). 256 threads.
// ---------------------------------------------------------------------------
#define PSTR 4136   // strip row stride (floats), 16B-aligned rows

__global__ void __launch_bounds__(256) convfull(const float* __restrict__ img,
                                                const float* __restrict__ cw,
                                                const float* __restrict__ cb) {
    __shared__ float PS[6][PSTR];

    const int hb = blockIdx.x;     // 0..7
    const int b  = blockIdx.y;     // 0..63
    const int t  = threadIdx.x;

    // fill 6 strip rows (hb*4-1 .. hb*4+4)
#pragma unroll
    for (int r = 0; r < 6; r++) {
        const int inrow = hb * 4 + r - 1;
        const bool ok = (unsigned)inrow < 32u;
        const float* rp = img + ((size_t)b * IMG_H + (ok ? inrow : 0)) * IMG_W;
        for (int pi = t; pi < PSTR; pi += 256) {
            const int g = pi - 13;
            float v = 0.0f;
            if (ok) v = ((unsigned)g < (unsigned)IMG_W) ? rp[g] : 1.0f;
            PS[r][pi] = v;
        }
    }

    float w[3][3];
#pragma unroll
    for (int i = 0; i < 3; i++)
#pragma unroll
        for (int j = 0; j < 3; j++) w[i][j] = cw[i * 3 + j];
    const float bias = cb[0];

    __syncthreads();

#pragma unroll
    for (int hh = 0; hh < 4; hh++) {
        const int h = hb * 4 + hh;
        const size_t base4 = ((size_t)b * IMG_H + h) * (FSTR / 4);
        for (int grp = t; grp < GI_MAX / 4; grp += 256) {
            const int gi0 = grp * 4;
            float q[3][8];
#pragma unroll
            for (int r = 0; r < 3; r++) {
                const float4 pa = *reinterpret_cast<const float4*>(&PS[hh + r][gi0]);
                const float4 pb = *reinterpret_cast<const float4*>(&PS[hh + r][gi0 + 4]);
                q[r][0] = pa.x; q[r][1] = pa.y; q[r][2] = pa.z; q[r][3] = pa.w;
                q[r][4] = pb.x; q[r][5] = pb.y; q[r][6] = pb.z; q[r][7] = pb.w;
            }
            float4 F, EL, ER;
            float* Fp = &F.x; float* ELp = &EL.x; float* ERp = &ER.x;
#pragma unroll
            for (int j = 0; j < 4; j++) {
                float f = bias, el = 0.0f, er = 0.0f;
#pragma unroll
                for (int r = 0; r < 3; r++) {
                    f  += w[r][0] * q[r][j] + w[r][1] * q[r][j + 1] + w[r][2] * q[r][j + 2];
                    el += w[r][0] * q[r][j];
                    er += w[r][2] * q[r][j + 2];
                }
                Fp[j] = f; ELp[j] = el; ERp[j] = er;
            }
            reinterpret_cast<float4*>(g_F )[base4 + grp] = F;
            reinterpret_cast<float4*>(g_EL)[base4 + grp] = EL;
            reinterpret_cast<float4*>(g_ER)[base4 + grp] = ER;
        }
    }
}

// ---------------------------------------------------------------------------
// Kernel 2: g_W[n][k] = tf32(lin_w[k][n])   (transpose + round)
// ---------------------------------------------------------------------------
__global__ void __launch_bounds__(256) prepw(const float* __restrict__ lw) {
    __shared__ float tl[32][33];
    const int tx = threadIdx.x & 31;
    const int ty = threadIdx.x >> 5;      // 0..7
    const int n0 = blockIdx.x * 32;
    const int k0 = blockIdx.y * 32;
#pragma unroll
    for (int i = 0; i < 4; i++)
        tl[ty + 8 * i][tx] = lw[(size_t)(k0 + ty + 8 * i) * NTOT + n0 + tx];
    __syncthreads();
#pragma unroll
    for (int i = 0; i < 4; i++)
        g_W[(size_t)(n0 + ty + 8 * i) * KTOT + k0 + tx] = to_tf32(tl[tx][ty + 8 * i]);
}

// ---------------------------------------------------------------------------
// Kernel 3: fused gather + tf32 GEMM (mma.sync m16n8k8 + ldmatrix).
// CTA tile 128(M) x 256(N); K-chunk 32 = one image row h; KCHUNKS = 32.
// A-tile built on the fly from F/EL/ER (register-prefetched one chunk ahead),
// double-buffered in smem (2 x 16KB). B via 3-stage cp.async ring (3 x 32KB).
// 256 threads, warp grid 2x4, warp tile 64x64.
// ---------------------------------------------------------------------------
#define A_STAGE  16384
#define B_STAGE  32768
#define B_BASE   (2 * A_STAGE)
#define GEMM_SMEM (B_BASE + 3 * B_STAGE)     // 128 KB
#define KCHUNKS  32

__global__ void __launch_bounds__(256) gemm(const float* __restrict__ bias,
                                            float* __restrict__ out) {
    extern __shared__ __align__(1024) char dsm[];

    const int t    = threadIdx.x;
    const int lane = t & 31;
    const int warp = t >> 5;
    const int wm   = warp >> 2;     // 0..1
    const int wn   = warp & 3;      // 0..3
    const int bx   = blockIdx.x;    // N block (0..1)
    const int by   = blockIdx.y;    // M block (0..255)

    const uint32_t smem_base = smem_u32(dsm);

    const int bB = by >> 2;                 // image index of this M tile
    const int s0 = (by & 3) * 128;          // first slice of this M tile

    // per-thread gather geometry (4 tasks: id = t + i*256 -> row, seg)
    int  g_row[4], g_seg[4];
    const float* g_fp[4];
    size_t eoff[4];
#pragma unroll
    for (int i = 0; i < 4; i++) {
        const int id = t + i * 256;
        g_row[i] = id >> 3;
        g_seg[i] = id & 7;
        // base for chunk h is added as h*FSTR each prefetch
        g_fp[i] = g_F + ((size_t)bB * IMG_H) * FSTR + (size_t)(s0 + g_row[i]) * 8 + g_seg[i] * 4;
        eoff[i] = ((size_t)bB * IMG_H) * FSTR + (size_t)(s0 + g_row[i]) * 8;
    }

    float4 pf[4]; float pel[4], per_[4];
    auto prefetchF = [&](int kc) {
        const size_t ho = (size_t)kc * FSTR;
#pragma unroll
        for (int i = 0; i < 4; i++) {
            pf[i] = *reinterpret_cast<const float4*>(g_fp[i] + ho);
            pel[i] = (g_seg[i] == 0) ? g_EL[eoff[i] + ho]      : 0.0f;
            per_[i] = (g_seg[i] == 7) ? g_ER[eoff[i] + ho + 31] : 0.0f;
        }
    };
    auto stsA = [&](int stage) {
        const uint32_t sa = smem_base + stage * A_STAGE;
#pragma unroll
        for (int i = 0; i < 4; i++) {
            float4 v = pf[i];
            v.x -= pel[i];
            v.w -= per_[i];
            v.x = to_tf32(fmaxf(v.x, 0.0f));
            v.y = to_tf32(fmaxf(v.y, 0.0f));
            v.z = to_tf32(fmaxf(v.z, 0.0f));
            v.w = to_tf32(fmaxf(v.w, 0.0f));
            const uint32_t off = g_row[i] * 128 + ((g_seg[i] ^ (g_row[i] & 7)) << 4);
            *reinterpret_cast<float4*>(dsm + (sa - smem_base) + off) = v;
        }
    };

    const char* Bgc = (const char*)(g_W + (size_t)(bx * 256) * KTOT);
    auto loadB = [&](int kc) {
        const uint32_t sb = smem_base + B_BASE + (kc % 3) * B_STAGE;
        const size_t kofs = (size_t)kc * 128;
#pragma unroll
        for (int i = 0; i < 8; i++) {
            const int id = t + i * 256;
            const int row = id >> 3, ch = id & 7;
            cpa16(sb + row * 128 + ((ch ^ (row & 7)) << 4),
                  Bgc + (size_t)row * 4096 + kofs + ch * 16);
        }
        cpa_commit();
    };

    float c[4][8][4];
#pragma unroll
    for (int i = 0; i < 4; i++)
#pragma unroll
        for (int j = 0; j < 8; j++)
#pragma unroll
            for (int k = 0; k < 4; k++) c[i][j][k] = 0.0f;

    // ---------------- prologue ----------------
    prefetchF(0);
    loadB(0);
    loadB(1);
    asm volatile("cp.async.wait_group 1;" ::: "memory");   // B(0) done
    stsA(0);
    prefetchF(1);
    __syncthreads();

    // ldmatrix per-lane address components (within a stage)
    const int rm     = lane & 7;
    const int a_roff = (wm * 64 + (lane & 15)) * 128;                      // + mt*2048
    const int a_m    = lane >> 4;
    const int b_roff = (wn * 64 + ((lane >> 4) << 3) + (lane & 7)) * 128;  // + p*2048
    const int b_m    = (lane >> 3) & 1;

    for (int kc = 0; kc < KCHUNKS; kc++) {
        const uint32_t sa = smem_base + (kc & 1) * A_STAGE;
        const uint32_t sb = smem_base + B_BASE + (kc % 3) * B_STAGE;

#pragma unroll
        for (int ks = 0; ks < 4; ks++) {
            uint32_t a[4][4], bfr[4][4];
#pragma unroll
            for (int mt = 0; mt < 4; mt++)
                ldsm_x4(a[mt], sa + a_roff + mt * 2048 + (((2 * ks + a_m) ^ rm) << 4));
#pragma unroll
            for (int p = 0; p < 4; p++)
                ldsm_x4(bfr[p], sb + b_roff + p * 2048 + (((2 * ks + b_m) ^ rm) << 4));
#pragma unroll
            for (int mt = 0; mt < 4; mt++)
#pragma unroll
                for (int p = 0; p < 4; p++) {
                    asm volatile(
                        "mma.sync.aligned.m16n8k8.row.col.f32.tf32.tf32.f32 "
                        "{%0,%1,%2,%3}, {%4,%5,%6,%7}, {%8,%9}, {%0,%1,%2,%3};"
                        : "+f"(c[mt][2 * p][0]), "+f"(c[mt][2 * p][1]),
                          "+f"(c[mt][2 * p][2]), "+f"(c[mt][2 * p][3])
                        : "r"(a[mt][0]), "r"(a[mt][1]), "r"(a[mt][2]), "r"(a[mt][3]),
                          "r"(bfr[p][0]), "r"(bfr[p][1]));
                    asm volatile(
                        "mma.sync.aligned.m16n8k8.row.col.f32.tf32.tf32.f32 "
                        "{%0,%1,%2,%3}, {%4,%5,%6,%7}, {%8,%9}, {%0,%1,%2,%3};"
                        : "+f"(c[mt][2 * p + 1][0]), "+f"(c[mt][2 * p + 1][1]),
                          "+f"(c[mt][2 * p + 1][2]), "+f"(c[mt][2 * p + 1][3])
                        : "r"(a[mt][0]), "r"(a[mt][1]), "r"(a[mt][2]), "r"(a[mt][3]),
                          "r"(bfr[p][2]), "r"(bfr[p][3]));
                }
        }

        if (kc < KCHUNKS - 1) {
            stsA((kc + 1) & 1);                       // build A for next chunk
            if (kc + 2 < KCHUNKS) {
                prefetchF(kc + 2);                    // regs for chunk after
                loadB(kc + 2);                        // into ring stage (kc+2)%3
            } else {
                cpa_commit();                         // keep group count in step
            }
            asm volatile("cp.async.wait_group 1;" ::: "memory");  // B(kc+1) ready
            __syncthreads();                          // A[next] visible; cur drained
        }
    }

    // ---------------- epilogue: += bias, write fp32 ----------------
#pragma unroll
    for (int nt = 0; nt < 8; nt++) {
        const int col = bx * 256 + wn * 64 + nt * 8 + 2 * (lane & 3);
        const float b0 = bias[col], b1 = bias[col + 1];
#pragma unroll
        for (int mt = 0; mt < 4; mt++) {
            const int r0 = by * 128 + wm * 64 + mt * 16 + (lane >> 2);
            float2 v0 = make_float2(c[mt][nt][0] + b0, c[mt][nt][1] + b1);
            float2 v1 = make_float2(c[mt][nt][2] + b0, c[mt][nt][3] + b1);
            *reinterpret_cast<float2*>(&out[(size_t)r0 * NTOT + col])       = v0;
            *reinterpret_cast<float2*>(&out[(size_t)(r0 + 8) * NTOT + col]) = v1;
        }
    }
}

// ---------------------------------------------------------------------------
extern "C" void kernel_launch(void* const* d_in, const int* in_sizes, int n_in,
                              void* d_out, int out_size) {
    const float* images = (const float*)d_in[0];
    const float* conv_w = (const float*)d_in[1];
    const float* conv_b = (const float*)d_in[2];
    const float* lin_w  = (const float*)d_in[3];
    const float* lin_b  = (const float*)d_in[4];
    float* out = (float*)d_out;

    cudaFuncSetAttribute(gemm, cudaFuncAttributeMaxDynamicSharedMemorySize,
                         GEMM_SMEM);

    convfull<<<dim3(IMG_H / 4, IMG_B), 256>>>(images, conv_w, conv_b);
    prepw<<<dim3(NTOT / 32, KTOT / 32), 256>>>(lin_w);
    gemm<<<dim3(NTOT / 256, MTOT / 128), 256, GEMM_SMEM>>>(lin_b, out);
}

// round 6
// speedup vs baseline: 1.8389x; 1.8389x over previous
#include <cuda_runtime.h>
#include <cuda_fp16.h>
#include <cstdint>
#include <cstddef>

#define IMG_B   64
#define IMG_H   32
#define IMG_W   4096
#define NSLICE  512
#define MTOT    32768
#define KTOT    1024
#define NTOT    512

// Scratch (static device arrays; no runtime allocation).
__device__ __align__(128) __half g_A[(size_t)MTOT * KTOT];   // 64 MB, M x K fp16
__device__ __align__(128) __half g_W[(size_t)NTOT * KTOT];   // 1 MB,  W^T fp16, N x K

// ---------------------------------------------------------------------------
// helpers
// ---------------------------------------------------------------------------
__device__ __forceinline__ uint32_t smem_u32(const void* p) {
    uint32_t a;
    asm("{ .reg .u64 t; cvta.to.shared.u64 t, %1; cvt.u32.u64 %0, t; }" : "=r"(a) : "l"(p));
    return a;
}

__device__ __forceinline__ void cpa16(uint32_t smem_addr, const void* gptr) {
    asm volatile("cp.async.cg.shared.global [%0], [%1], 16;" :: "r"(smem_addr), "l"(gptr));
}
__device__ __forceinline__ void cpa_commit() {
    asm volatile("cp.async.commit_group;" ::: "memory");
}

__device__ __forceinline__ void ldsm_x4(uint32_t r[4], uint32_t addr) {
    asm volatile("ldmatrix.sync.aligned.m8n8.x4.shared.b16 {%0,%1,%2,%3}, [%4];"
                 : "=r"(r[0]), "=r"(r[1]), "=r"(r[2]), "=r"(r[3]) : "r"(addr));
}

__device__ __forceinline__ void mma_f16(float c[4], const uint32_t a[4],
                                        uint32_t b0, uint32_t b1) {
    asm volatile(
        "mma.sync.aligned.m16n8k16.row.col.f32.f16.f16.f32 "
        "{%0,%1,%2,%3}, {%4,%5,%6,%7}, {%8,%9}, {%0,%1,%2,%3};"
        : "+f"(c[0]), "+f"(c[1]), "+f"(c[2]), "+f"(c[3])
        : "r"(a[0]), "r"(a[1]), "r"(a[2]), "r"(a[3]), "r"(b0), "r"(b1));
}

// ---------------------------------------------------------------------------
// Kernel 1 (abuild): shared full-image conv row in smem + per-slice edge fixup
// + ReLU + fp16 -> g_A.   Grid (2 halves, IMG_H, IMG_B), 256 threads.
//
// Strip covers g in [O-13, O-13+SPAN). For slice s = half*256+t, col c:
//   j = 8t + c (local F index), F[j] window = PS[r][j..j+2].
//   c==0  subtract t0 = sum_r w[r][0]*PS[r][j]      (stored compact at j%8==0)
//   c==31 subtract t2 = sum_r w[r][2]*PS[r][j+2]    (stored compact at j%8==7)
// Rows outside [0,32) are 0 (vertical zero pad); cols outside [0,4096) are 1.0.
// ---------------------------------------------------------------------------
#define SPAN   2080
#define JMAX   2074
#define FIDX(j) ((j) + ((j) >> 3))     // conflict-free padded FS index

__global__ void __launch_bounds__(256) abuild(const float* __restrict__ img,
                                              const float* __restrict__ cw,
                                              const float* __restrict__ cb) {
    __shared__ float PS[3][SPAN];
    __shared__ float FS[JMAX + JMAX / 8 + 8];
    __shared__ float ELS[264], ERS[264];

    const int half = blockIdx.x;
    const int h    = blockIdx.y;
    const int b    = blockIdx.z;
    const int t    = threadIdx.x;

    const int O = half * 2048;           // global gi origin; strip g0 = O - 13

    // fill 3 padded rows (h-1, h, h+1)
#pragma unroll
    for (int r = 0; r < 3; r++) {
        const int inrow = h + r - 1;
        const bool ok = (unsigned)inrow < 32u;
        const float* rp = img + ((size_t)b * IMG_H + (ok ? inrow : 0)) * IMG_W;
        for (int pi = t; pi < SPAN; pi += 256) {
            const int g = O - 13 + pi;
            float v = 0.0f;
            if (ok) v = ((unsigned)g < (unsigned)IMG_W) ? rp[g] : 1.0f;
            PS[r][pi] = v;
        }
    }

    float w[3][3];
#pragma unroll
    for (int i = 0; i < 3; i++)
#pragma unroll
        for (int j = 0; j < 3; j++) w[i][j] = cw[i * 3 + j];
    const float bias = cb[0];

    __syncthreads();

    // shared F row + compact edge partial sums
    for (int j = t; j < JMAX; j += 256) {
        float t0 = 0.0f, t1 = 0.0f, t2 = 0.0f;
#pragma unroll
        for (int r = 0; r < 3; r++) {
            t0 += w[r][0] * PS[r][j];
            t1 += w[r][1] * PS[r][j + 1];
            t2 += w[r][2] * PS[r][j + 2];
        }
        FS[FIDX(j)] = bias + t0 + t1 + t2;
        const int jm = j & 7;
        if (jm == 0) ELS[j >> 3] = t0;
        if (jm == 7) ERS[j >> 3] = t2;
    }

    __syncthreads();

    // gather 32 values for slice s = half*256 + t, fix edges, relu, fp16 store
    const int s = half * 256 + t;
    char* op = (char*)g_A + ((size_t)(b * NSLICE + s) * KTOT + h * 32) * 2;
    const int base = 9 * t;              // FIDX(8t + c) = 9t + c + (c>>3)

#pragma unroll
    for (int c8 = 0; c8 < 4; c8++) {
        float v[8];
#pragma unroll
        for (int cc = 0; cc < 8; cc++) {
            const int c = c8 * 8 + cc;
            v[cc] = FS[base + c + (c >> 3)];
        }
        if (c8 == 0) v[0] -= ELS[t];
        if (c8 == 3) v[7] -= ERS[t + 3];
        uint4 u;
        __half2* hp = reinterpret_cast<__half2*>(&u);
#pragma unroll
        for (int i = 0; i < 4; i++)
            hp[i] = __floats2half2_rn(fmaxf(v[2 * i], 0.0f),
                                      fmaxf(v[2 * i + 1], 0.0f));
        *reinterpret_cast<uint4*>(op + c8 * 16) = u;
    }
}

// ---------------------------------------------------------------------------
// Kernel 2: g_W[n][k] = fp16(lin_w[k][n])   (transpose + round)
// ---------------------------------------------------------------------------
__global__ void __launch_bounds__(256) prepw(const float* __restrict__ lw) {
    __shared__ float tl[32][33];
    const int tx = threadIdx.x & 31;
    const int ty = threadIdx.x >> 5;      // 0..7
    const int n0 = blockIdx.x * 32;
    const int k0 = blockIdx.y * 32;
#pragma unroll
    for (int i = 0; i < 4; i++)
        tl[ty + 8 * i][tx] = lw[(size_t)(k0 + ty + 8 * i) * NTOT + n0 + tx];
    __syncthreads();
#pragma unroll
    for (int i = 0; i < 4; i++)
        g_W[(size_t)(n0 + ty + 8 * i) * KTOT + k0 + tx] =
            __float2half_rn(tl[tx][ty + 8 * i]);
}

// ---------------------------------------------------------------------------
// Kernel 3: fp16 GEMM, mma.sync m16n8k16 + ldmatrix.
// CTA tile 128(M) x 256(N), BK=64 halves (128B rows). 512 threads, warp grid
// 2(m) x 8(n), warp tile 64x32. 3-stage cp.async ring (A 16KB + B 32KB per
// stage = 144KB). XOR swizzle (chunk ^= row&7) conflict-free for stores+ldsm.
// ---------------------------------------------------------------------------
#define A_STAGE   16384
#define B_STAGE   32768
#define STAGE_SZ  (A_STAGE + B_STAGE)
#define GEMM_SMEM (3 * STAGE_SZ)          // 144 KB
#define KCHUNKS   16

__global__ void __launch_bounds__(512) gemm(const float* __restrict__ bias,
                                            float* __restrict__ out) {
    extern __shared__ __align__(1024) char dsm[];

    const int t    = threadIdx.x;
    const int lane = t & 31;
    const int warp = t >> 5;
    const int wm   = warp >> 3;     // 0..1
    const int wn   = warp & 7;      // 0..7
    const int bx   = blockIdx.x;    // N block (0..1)
    const int by   = blockIdx.y;    // M block (0..255)

    const uint32_t smem_base = smem_u32(dsm);

    const char* Agc = (const char*)g_A + (size_t)(by * 128) * (KTOT * 2);
    const char* Bgc = (const char*)g_W + (size_t)(bx * 256) * (KTOT * 2);

    auto load_chunk = [&](int kc) {
        const uint32_t sa = smem_base + (kc % 3) * STAGE_SZ;
        const uint32_t sb = sa + A_STAGE;
        const size_t kofs = (size_t)kc * 128;     // bytes into each 2048B K-row
#pragma unroll
        for (int i = 0; i < 2; i++) {             // A: 1024 16B-chunks
            const int id = t + i * 512;
            const int row = id >> 3, ch = id & 7;
            cpa16(sa + row * 128 + ((ch ^ (row & 7)) << 4),
                  Agc + (size_t)row * 2048 + kofs + ch * 16);
        }
#pragma unroll
        for (int i = 0; i < 4; i++) {             // B: 2048 16B-chunks
            const int id = t + i * 512;
            const int row = id >> 3, ch = id & 7;
            cpa16(sb + row * 128 + ((ch ^ (row & 7)) << 4),
                  Bgc + (size_t)row * 2048 + kofs + ch * 16);
        }
        cpa_commit();
    };

    float c[4][2][2][4];                          // [mt][p][nsub][4]
#pragma unroll
    for (int i = 0; i < 4; i++)
#pragma unroll
        for (int j = 0; j < 2; j++)
#pragma unroll
            for (int k = 0; k < 2; k++)
#pragma unroll
                for (int l = 0; l < 4; l++) c[i][j][k][l] = 0.0f;

    load_chunk(0);
    load_chunk(1);

    // ldmatrix per-lane address components (within a stage)
    const int rm     = lane & 7;
    const int a_roff = (wm * 64 + (lane & 15)) * 128;                      // + mt*2048
    const int a_m    = lane >> 4;                                          // chunk add
    const int b_roff = (wn * 32 + ((lane >> 4) << 3) + (lane & 7)) * 128;  // + p*2048
    const int b_m    = (lane >> 3) & 1;                                    // chunk add

    for (int kc = 0; kc < KCHUNKS; kc++) {
        asm volatile("cp.async.wait_group 1;" ::: "memory");  // chunk kc ready
        __syncthreads();                                      // + prev compute done

        if (kc + 2 < KCHUNKS) load_chunk(kc + 2);             // freed stage
        else                  cpa_commit();                   // keep counts aligned

        const uint32_t sa = smem_base + (kc % 3) * STAGE_SZ;
        const uint32_t sb = sa + A_STAGE;

#pragma unroll
        for (int ks = 0; ks < 4; ks++) {                      // k16 steps
            uint32_t a[4][4], bf[2][4];
#pragma unroll
            for (int mt = 0; mt < 4; mt++)
                ldsm_x4(a[mt], sa + a_roff + mt * 2048 +
                               (((2 * ks + a_m) ^ rm) << 4));
#pragma unroll
            for (int p = 0; p < 2; p++)
                ldsm_x4(bf[p], sb + b_roff + p * 2048 +
                               (((2 * ks + b_m) ^ rm) << 4));
#pragma unroll
            for (int mt = 0; mt < 4; mt++)
#pragma unroll
                for (int p = 0; p < 2; p++) {
                    mma_f16(c[mt][p][0], a[mt], bf[p][0], bf[p][1]);
                    mma_f16(c[mt][p][1], a[mt], bf[p][2], bf[p][3]);
                }
        }
    }

    // epilogue: += bias, write fp32
#pragma unroll
    for (int p = 0; p < 2; p++)
#pragma unroll
        for (int ns = 0; ns < 2; ns++) {
            const int col = bx * 256 + wn * 32 + p * 16 + ns * 8 + 2 * (lane & 3);
            const float b0 = bias[col], b1 = bias[col + 1];
#pragma unroll
            for (int mt = 0; mt < 4; mt++) {
                const int r0 = by * 128 + wm * 64 + mt * 16 + (lane >> 2);
                float2 v0 = make_float2(c[mt][p][ns][0] + b0, c[mt][p][ns][1] + b1);
                float2 v1 = make_float2(c[mt][p][ns][2] + b0, c[mt][p][ns][3] + b1);
                *reinterpret_cast<float2*>(&out[(size_t)r0 * NTOT + col])       = v0;
                *reinterpret_cast<float2*>(&out[(size_t)(r0 + 8) * NTOT + col]) = v1;
            }
        }
}

// ---------------------------------------------------------------------------
extern "C" void kernel_launch(void* const* d_in, const int* in_sizes, int n_in,
                              void* d_out, int out_size) {
    const float* images = (const float*)d_in[0];
    const float* conv_w = (const float*)d_in[1];
    const float* conv_b = (const float*)d_in[2];
    const float* lin_w  = (const float*)d_in[3];
    const float* lin_b  = (const float*)d_in[4];
    float* out = (float*)d_out;

    cudaFuncSetAttribute(gemm, cudaFuncAttributeMaxDynamicSharedMemorySize,
                         GEMM_SMEM);

    abuild<<<dim3(2, IMG_H, IMG_B), 256>>>(images, conv_w, conv_b);
    prepw<<<dim3(NTOT / 32, KTOT / 32), 256>>>(lin_w);
    gemm<<<dim3(NTOT / 256, MTOT / 128), 512, GEMM_SMEM>>>(lin_b, out);
}

// round 7
// speedup vs baseline: 1.8880x; 1.0267x over previous
#include <cuda_runtime.h>
#include <cuda_fp16.h>
#include <cstdint>
#include <cstddef>

#define IMG_B   64
#define IMG_H   32
#define IMG_W   4096
#define NSLICE  512
#define MTOT    32768
#define KTOT    1024
#define NTOT    512

// Tiled + pre-swizzled operand storage (see gemm for layout).
//   g_A: [m_tile 0..255][kc 0..15][row 0..127][16B chunk, ch^(row&7)]  -> 64 MB
//   g_W: [bx 0..1][kc 0..15][row 0..255][16B chunk, ch^(row&7)]        -> 1 MB
__device__ __align__(128) __half g_A[(size_t)MTOT * KTOT];
__device__ __align__(128) __half g_W[(size_t)NTOT * KTOT];

// ---------------------------------------------------------------------------
// helpers
// ---------------------------------------------------------------------------
__device__ __forceinline__ uint32_t smem_u32(const void* p) {
    uint32_t a;
    asm("{ .reg .u64 t; cvta.to.shared.u64 t, %1; cvt.u32.u64 %0, t; }" : "=r"(a) : "l"(p));
    return a;
}

__device__ __forceinline__ void ldsm_x4(uint32_t r[4], uint32_t addr) {
    asm volatile("ldmatrix.sync.aligned.m8n8.x4.shared.b16 {%0,%1,%2,%3}, [%4];"
                 : "=r"(r[0]), "=r"(r[1]), "=r"(r[2]), "=r"(r[3]) : "r"(addr));
}

__device__ __forceinline__ void mma_f16(float c[4], const uint32_t a[4],
                                        uint32_t b0, uint32_t b1) {
    asm volatile(
        "mma.sync.aligned.m16n8k16.row.col.f32.f16.f16.f32 "
        "{%0,%1,%2,%3}, {%4,%5,%6,%7}, {%8,%9}, {%0,%1,%2,%3};"
        : "+f"(c[0]), "+f"(c[1]), "+f"(c[2]), "+f"(c[3])
        : "r"(a[0]), "r"(a[1]), "r"(a[2]), "r"(a[3]), "r"(b0), "r"(b1));
}

__device__ __forceinline__ void bulk_g2s(uint32_t sdst, const void* gsrc,
                                         uint32_t bytes, uint32_t mbar) {
    asm volatile(
        "cp.async.bulk.shared::cluster.global.mbarrier::complete_tx::bytes "
        "[%0], [%1], %2, [%3];"
        :: "r"(sdst), "l"(gsrc), "r"(bytes), "r"(mbar) : "memory");
}

#define MBARRIER_INIT(a, c) \
    asm volatile("mbarrier.init.shared.b64 [%0], %1;" :: "r"((uint32_t)(a)), "r"((uint32_t)(c)) : "memory")
#define MBARRIER_EXPECT_TX(a, b) \
    asm volatile("mbarrier.arrive.expect_tx.shared.b64 _, [%0], %1;" :: "r"((uint32_t)(a)), "r"((uint32_t)(b)) : "memory")

#define MBARRIER_WAIT_PARITY(mbar_addr, parity) do { \
    uint32_t _mbar = (uint32_t)(mbar_addr); \
    uint32_t _par  = (uint32_t)(parity); \
    uint32_t _done_; \
    asm volatile("{\n\t.reg .pred p;\n\t" \
        "mbarrier.try_wait.parity.acquire.cta.shared::cta.b64 p, [%1], %2;\n\t" \
        "selp.b32 %0, 1, 0, p;\n\t}" \
        : "=r"(_done_) : "r"(_mbar), "r"(_par) : "memory"); \
    if (!_done_) { \
        asm volatile("{\n\t.reg .pred P1;\n\t" \
            "WAIT_LOOP_%=:\n\t" \
            "mbarrier.try_wait.parity.acquire.cta.shared::cta.b64 P1, [%0], %1, 0x989680;\n\t" \
            "@P1 bra.uni WAIT_DONE_%=;\n\t" \
            "bra.uni WAIT_LOOP_%=;\n\t" \
            "WAIT_DONE_%=:\n\t}" \
            :: "r"(_mbar), "r"(_par) : "memory"); \
    } \
} while (0)

// ---------------------------------------------------------------------------
// Kernel 1 (abuild): shared full-image conv row in smem + per-slice edge fixup
// + ReLU + fp16 -> g_A (tiled, pre-swizzled). Grid (2, IMG_H, IMG_B), 256 thr.
// ---------------------------------------------------------------------------
#define SPAN   2080
#define JMAX   2074
#define FIDX(j) ((j) + ((j) >> 3))

__global__ void __launch_bounds__(256) abuild(const float* __restrict__ img,
                                              const float* __restrict__ cw,
                                              const float* __restrict__ cb) {
    __shared__ float PS[3][SPAN];
    __shared__ float FS[JMAX + JMAX / 8 + 8];
    __shared__ float ELS[264], ERS[264];

    const int half = blockIdx.x;
    const int h    = blockIdx.y;
    const int b    = blockIdx.z;
    const int t    = threadIdx.x;

    const int O = half * 2048;

#pragma unroll
    for (int r = 0; r < 3; r++) {
        const int inrow = h + r - 1;
        const bool ok = (unsigned)inrow < 32u;
        const float* rp = img + ((size_t)b * IMG_H + (ok ? inrow : 0)) * IMG_W;
        for (int pi = t; pi < SPAN; pi += 256) {
            const int g = O - 13 + pi;
            float v = 0.0f;
            if (ok) v = ((unsigned)g < (unsigned)IMG_W) ? rp[g] : 1.0f;
            PS[r][pi] = v;
        }
    }

    float w[3][3];
#pragma unroll
    for (int i = 0; i < 3; i++)
#pragma unroll
        for (int j = 0; j < 3; j++) w[i][j] = cw[i * 3 + j];
    const float bias = cb[0];

    __syncthreads();

    for (int j = t; j < JMAX; j += 256) {
        float t0 = 0.0f, t1 = 0.0f, t2 = 0.0f;
#pragma unroll
        for (int r = 0; r < 3; r++) {
            t0 += w[r][0] * PS[r][j];
            t1 += w[r][1] * PS[r][j + 1];
            t2 += w[r][2] * PS[r][j + 2];
        }
        FS[FIDX(j)] = bias + t0 + t1 + t2;
        const int jm = j & 7;
        if (jm == 0) ELS[j >> 3] = t0;
        if (jm == 7) ERS[j >> 3] = t2;
    }

    __syncthreads();

    // slice s = half*256 + t -> tiled A address
    const int s = half * 256 + t;
    const size_t gm = (size_t)b * NSLICE + s;
    const size_t mtile = gm >> 7;
    const int row = (int)(gm & 127);
    const int kc = h >> 1, hi = h & 1;
    char* base = (char*)g_A + (mtile * 16 + kc) * 16384 + (size_t)row * 128;

    const int fbase = 9 * t;
#pragma unroll
    for (int c8 = 0; c8 < 4; c8++) {
        float v[8];
#pragma unroll
        for (int cc = 0; cc < 8; cc++) {
            const int c = c8 * 8 + cc;
            v[cc] = FS[fbase + c + (c >> 3)];
        }
        if (c8 == 0) v[0] -= ELS[t];
        if (c8 == 3) v[7] -= ERS[t + 3];
        uint4 u;
        __half2* hp = reinterpret_cast<__half2*>(&u);
#pragma unroll
        for (int i = 0; i < 4; i++)
            hp[i] = __floats2half2_rn(fmaxf(v[2 * i], 0.0f),
                                      fmaxf(v[2 * i + 1], 0.0f));
        const int ch = hi * 4 + c8;
        *reinterpret_cast<uint4*>(base + ((ch ^ (row & 7)) << 4)) = u;
    }
}

// ---------------------------------------------------------------------------
// Kernel 2: g_W tiled/pre-swizzled fp16 of lin_w^T.
// ---------------------------------------------------------------------------
__global__ void __launch_bounds__(256) prepw(const float* __restrict__ lw) {
    __shared__ float tl[32][33];
    const int tx = threadIdx.x & 31;
    const int ty = threadIdx.x >> 5;      // 0..7
    const int n0 = blockIdx.x * 32;
    const int k0 = blockIdx.y * 32;
#pragma unroll
    for (int i = 0; i < 4; i++)
        tl[ty + 8 * i][tx] = lw[(size_t)(k0 + ty + 8 * i) * NTOT + n0 + tx];
    __syncthreads();
    const int k = k0 + tx;
    const int kc = k >> 6, col = k & 63;
    const int ch = col >> 3, off = (col & 7) * 2;
#pragma unroll
    for (int i = 0; i < 4; i++) {
        const int n = n0 + ty + 8 * i;
        const int bxW = n >> 8, rowW = n & 255;
        char* p = (char*)g_W + ((size_t)(bxW * 16 + kc) * 256 + rowW) * 128 +
                  ((ch ^ (rowW & 7)) << 4) + off;
        *reinterpret_cast<__half*>(p) = __float2half_rn(tl[tx][ty + 8 * i]);
    }
}

// ---------------------------------------------------------------------------
// Kernel 3: fp16 GEMM, mma.sync m16n8k16 + ldmatrix; operands streamed with
// cp.async.bulk (UBLKCP) + mbarrier (no per-thread LDGSTS). CTA tile 128x256,
// BK=64 halves; 3-stage ring (48KB/stage, 144KB). 512 threads, warps 2x8,
// warp tile 64x32. Tiles are pre-swizzled in gmem: bulk copy reproduces the
// XOR-swizzled smem image, so ldmatrix addressing is conflict-free unchanged.
// ---------------------------------------------------------------------------
#define A_STAGE   16384
#define B_STAGE   32768
#define STAGE_SZ  (A_STAGE + B_STAGE)
#define GEMM_SMEM (3 * STAGE_SZ)          // 144 KB dynamic
#define KCHUNKS   16

__global__ void __launch_bounds__(512) gemm(const float* __restrict__ bias,
                                            float* __restrict__ out) {
    extern __shared__ __align__(1024) char dsm[];
    __shared__ __align__(16) uint64_t mbar[3];

    const int t    = threadIdx.x;
    const int lane = t & 31;
    const int warp = t >> 5;
    const int wm   = warp >> 3;     // 0..1
    const int wn   = warp & 7;      // 0..7
    const int bx   = blockIdx.x;    // N block (0..1)
    const int by   = blockIdx.y;    // M block (0..255)

    const uint32_t smem_base = smem_u32(dsm);
    uint32_t mb[3];
#pragma unroll
    for (int i = 0; i < 3; i++) mb[i] = smem_u32(&mbar[i]);

    const char* Abase = (const char*)g_A + (size_t)by * 16 * 16384;
    const char* Bbase = (const char*)g_W + (size_t)bx * 16 * 32768;

    if (t == 0) {
        MBARRIER_INIT(mb[0], 1);
        MBARRIER_INIT(mb[1], 1);
        MBARRIER_INIT(mb[2], 1);
        asm volatile("fence.proxy.async.shared::cta;" ::: "memory");
    }
    __syncthreads();

    auto issue = [&](int kc) {
        const int s = kc % 3;
        const uint32_t sa = smem_base + s * STAGE_SZ;
        MBARRIER_EXPECT_TX(mb[s], STAGE_SZ);
        bulk_g2s(sa,           Abase + (size_t)kc * A_STAGE, A_STAGE, mb[s]);
        bulk_g2s(sa + A_STAGE, Bbase + (size_t)kc * B_STAGE, B_STAGE, mb[s]);
    };

    if (t == 0) { issue(0); issue(1); issue(2); }

    float c[4][2][2][4];
#pragma unroll
    for (int i = 0; i < 4; i++)
#pragma unroll
        for (int j = 0; j < 2; j++)
#pragma unroll
            for (int k = 0; k < 2; k++)
#pragma unroll
                for (int l = 0; l < 4; l++) c[i][j][k][l] = 0.0f;

    // ldmatrix per-lane address components (within a stage)
    const int rm     = lane & 7;
    const int a_roff = (wm * 64 + (lane & 15)) * 128;                      // + mt*2048
    const int a_m    = lane >> 4;
    const int b_roff = (wn * 32 + ((lane >> 4) << 3) + (lane & 7)) * 128;  // + p*2048
    const int b_m    = (lane >> 3) & 1;

    for (int kc = 0; kc < KCHUNKS; kc++) {
        const int st = kc % 3;
        MBARRIER_WAIT_PARITY(mb[st], (kc / 3) & 1);

        const uint32_t sa = smem_base + st * STAGE_SZ;
        const uint32_t sb = sa + A_STAGE;

#pragma unroll
        for (int ks = 0; ks < 4; ks++) {                      // k16 steps
            uint32_t a[4][4], bf[2][4];
#pragma unroll
            for (int mt = 0; mt < 4; mt++)
                ldsm_x4(a[mt], sa + a_roff + mt * 2048 +
                               (((2 * ks + a_m) ^ rm) << 4));
#pragma unroll
            for (int p = 0; p < 2; p++)
                ldsm_x4(bf[p], sb + b_roff + p * 2048 +
                               (((2 * ks + b_m) ^ rm) << 4));
#pragma unroll
            for (int mt = 0; mt < 4; mt++)
#pragma unroll
                for (int p = 0; p < 2; p++) {
                    mma_f16(c[mt][p][0], a[mt], bf[p][0], bf[p][1]);
                    mma_f16(c[mt][p][1], a[mt], bf[p][2], bf[p][3]);
                }
        }

        __syncthreads();                    // all warps done reading stage st
        if (t == 0 && kc + 3 < KCHUNKS) issue(kc + 3);
    }

    // epilogue: += bias, write fp32
#pragma unroll
    for (int p = 0; p < 2; p++)
#pragma unroll
        for (int ns = 0; ns < 2; ns++) {
            const int col = bx * 256 + wn * 32 + p * 16 + ns * 8 + 2 * (lane & 3);
            const float b0 = bias[col], b1 = bias[col + 1];
#pragma unroll
            for (int mt = 0; mt < 4; mt++) {
                const int r0 = by * 128 + wm * 64 + mt * 16 + (lane >> 2);
                float2 v0 = make_float2(c[mt][p][ns][0] + b0, c[mt][p][ns][1] + b1);
                float2 v1 = make_float2(c[mt][p][ns][2] + b0, c[mt][p][ns][3] + b1);
                *reinterpret_cast<float2*>(&out[(size_t)r0 * NTOT + col])       = v0;
                *reinterpret_cast<float2*>(&out[(size_t)(r0 + 8) * NTOT + col]) = v1;
            }
        }
}

// ---------------------------------------------------------------------------
extern "C" void kernel_launch(void* const* d_in, const int* in_sizes, int n_in,
                              void* d_out, int out_size) {
    const float* images = (const float*)d_in[0];
    const float* conv_w = (const float*)d_in[1];
    const float* conv_b = (const float*)d_in[2];
    const float* lin_w  = (const float*)d_in[3];
    const float* lin_b  = (const float*)d_in[4];
    float* out = (float*)d_out;

    cudaFuncSetAttribute(gemm, cudaFuncAttributeMaxDynamicSharedMemorySize,
                         GEMM_SMEM);

    abuild<<<dim3(2, IMG_H, IMG_B), 256>>>(images, conv_w, conv_b);
    prepw<<<dim3(NTOT / 32, KTOT / 32), 256>>>(lin_w);
    gemm<<<dim3(NTOT / 256, MTOT / 128), 512, GEMM_SMEM>>>(lin_b, out);
}

// round 10
// speedup vs baseline: 2.1897x; 1.1598x over previous
#include <cuda_runtime.h>
#include <cuda_fp16.h>
#include <cstdint>
#include <cstddef>

#define IMG_B   64
#define IMG_H   32
#define IMG_W   4096
#define NSLICE  512
#define MTOT    32768
#define KTOT    1024
#define NTOT    512

// Tiled + pre-swizzled operand storage (round-7 layout).
//   g_A: [m_tile 0..255][kc 0..15][row 0..127][16B chunk, ch^(row&7)]  64 MB
//   g_W: [bx 0..1][kc 0..15][row 0..255][16B chunk, ch^(row&7)]        1 MB
__device__ __align__(128) __half g_A[(size_t)MTOT * KTOT];
__device__ __align__(128) __half g_W[(size_t)NTOT * KTOT];

// ---------------------------------------------------------------------------
// helpers
// ---------------------------------------------------------------------------
__device__ __forceinline__ uint32_t smem_u32(const void* p) {
    uint32_t a;
    asm("{ .reg .u64 t; cvta.to.shared.u64 t, %1; cvt.u32.u64 %0, t; }" : "=r"(a) : "l"(p));
    return a;
}

__device__ __forceinline__ void ldsm_x4(uint32_t r[4], uint32_t addr) {
    asm volatile("ldmatrix.sync.aligned.m8n8.x4.shared.b16 {%0,%1,%2,%3}, [%4];"
                 : "=r"(r[0]), "=r"(r[1]), "=r"(r[2]), "=r"(r[3]) : "r"(addr));
}

__device__ __forceinline__ void mma_f16(float c[4], const uint32_t a[4],
                                        uint32_t b0, uint32_t b1) {
    asm volatile(
        "mma.sync.aligned.m16n8k16.row.col.f32.f16.f16.f32 "
        "{%0,%1,%2,%3}, {%4,%5,%6,%7}, {%8,%9}, {%0,%1,%2,%3};"
        : "+f"(c[0]), "+f"(c[1]), "+f"(c[2]), "+f"(c[3])
        : "r"(a[0]), "r"(a[1]), "r"(a[2]), "r"(a[3]), "r"(b0), "r"(b1));
}

__device__ __forceinline__ void bulk_g2s(uint32_t sdst, const void* gsrc,
                                         uint32_t bytes, uint32_t mbar) {
    asm volatile(
        "cp.async.bulk.shared::cluster.global.mbarrier::complete_tx::bytes "
        "[%0], [%1], %2, [%3];"
        :: "r"(sdst), "l"(gsrc), "r"(bytes), "r"(mbar) : "memory");
}

#define MBARRIER_INIT(a, c) \
    asm volatile("mbarrier.init.shared.b64 [%0], %1;" :: "r"((uint32_t)(a)), "r"((uint32_t)(c)) : "memory")
#define MBARRIER_EXPECT_TX(a, b) \
    asm volatile("mbarrier.arrive.expect_tx.shared.b64 _, [%0], %1;" :: "r"((uint32_t)(a)), "r"((uint32_t)(b)) : "memory")

#define MBARRIER_WAIT_PARITY(mbar_addr, parity) do { \
    uint32_t _mbar = (uint32_t)(mbar_addr); \
    uint32_t _par  = (uint32_t)(parity); \
    uint32_t _done_; \
    asm volatile("{\n\t.reg .pred p;\n\t" \
        "mbarrier.try_wait.parity.acquire.cta.shared::cta.b64 p, [%1], %2;\n\t" \
        "selp.b32 %0, 1, 0, p;\n\t}" \
        : "=r"(_done_) : "r"(_mbar), "r"(_par) : "memory"); \
    if (!_done_) { \
        asm volatile("{\n\t.reg .pred P1;\n\t" \
            "WAIT_LOOP_%=:\n\t" \
            "mbarrier.try_wait.parity.acquire.cta.shared::cta.b64 P1, [%0], %1, 0x989680;\n\t" \
            "@P1 bra.uni WAIT_DONE_%=;\n\t" \
            "bra.uni WAIT_LOOP_%=;\n\t" \
            "WAIT_DONE_%=:\n\t}" \
            :: "r"(_mbar), "r"(_par) : "memory"); \
    } \
} while (0)

// ---------------------------------------------------------------------------
// Kernel 1 (abuild v3): 2 h-rows per block, 512 threads.
// Phase1: fill 4 padded image rows (fp32) with float4 loads (no straddles:
//         all image boundaries are 0 mod 4 after the O-16 origin shift).
// Phase2: F row + edge partials, 4 outputs/iter (1 LDS.128 + 2 LDS.32 per row).
// Phase3: per-thread slice gather + edge fixup + ReLU + fp16 swizzled store.
// Grid (2 halves, 16 h-pairs, 64 b).
// ---------------------------------------------------------------------------
#define SPAN    2088            // padded strip length (522 float4)
#define NGRP    519             // groups of 4 F outputs per h row
#define FSSZ    2336            // >= FIDX(2075)+1
#define FIDX(j) ((j) + ((j) >> 3))

__global__ void __launch_bounds__(512) abuild(const float* __restrict__ img,
                                              const float* __restrict__ cw,
                                              const float* __restrict__ cb) {
    __shared__ float PS[4][SPAN];
    __shared__ float FS[2][FSSZ];
    __shared__ float ELS[2][260], ERS[2][260];

    const int half = blockIdx.x;
    const int hp   = blockIdx.y;         // h pair: rows 2hp, 2hp+1
    const int b    = blockIdx.z;
    const int t    = threadIdx.x;

    const int O = half * 2048;           // strip: g = O - 16 + 4*pi4

    float w[3][3];
#pragma unroll
    for (int i = 0; i < 3; i++)
#pragma unroll
        for (int j = 0; j < 3; j++) w[i][j] = cw[i * 3 + j];
    const float bias = cb[0];

    // interior float4 range [lo4, hi4] (outside: all-1.0 pad or zero row)
    const int lo4 = (half == 0) ? 4 : 0;
    const int hi4 = (half == 0) ? 521 : 515;

    // ---- phase 1: 4 rows x 522 float4 tasks ----
    for (int idx = t; idx < 4 * 522; idx += 512) {
        const int r   = idx / 522;
        const int pi4 = idx - r * 522;
        const int inrow = 2 * hp + r - 1;
        float4 v;
        if ((unsigned)inrow >= 32u) {
            v = make_float4(0.f, 0.f, 0.f, 0.f);
        } else if (pi4 >= lo4 && pi4 <= hi4) {
            const float* rp = img + ((size_t)b * IMG_H + inrow) * IMG_W;
            v = *reinterpret_cast<const float4*>(rp + (O - 16 + pi4 * 4));
        } else {
            v = make_float4(1.f, 1.f, 1.f, 1.f);
        }
        *reinterpret_cast<float4*>(&PS[r][pi4 * 4]) = v;
    }
    __syncthreads();

    // ---- phase 2: F rows + edge partials; 4 outputs per task ----
    for (int idx = t; idx < 2 * NGRP; idx += 512) {
        const int hrow = idx / NGRP;
        const int grp  = idx - hrow * NGRP;
        const int j    = grp * 4;

        float s3[3], s8[3];
        float4 q1[3];
#pragma unroll
        for (int r = 0; r < 3; r++) {
            const float* pr = PS[hrow + r];
            s3[r] = pr[j + 3];
            q1[r] = *reinterpret_cast<const float4*>(pr + j + 4);
            s8[r] = pr[j + 8];
        }
        float f[4], t0_0 = 0.f, t2_3 = 0.f;
#pragma unroll
        for (int jj = 0; jj < 4; jj++) f[jj] = bias;
#pragma unroll
        for (int r = 0; r < 3; r++) {
            const float a0 = s3[r], a1 = q1[r].x, a2 = q1[r].y,
                        a3 = q1[r].z, a4 = q1[r].w, a5 = s8[r];
            f[0] += w[r][0] * a0 + w[r][1] * a1 + w[r][2] * a2;
            f[1] += w[r][0] * a1 + w[r][1] * a2 + w[r][2] * a3;
            f[2] += w[r][0] * a2 + w[r][1] * a3 + w[r][2] * a4;
            f[3] += w[r][0] * a3 + w[r][1] * a4 + w[r][2] * a5;
            t0_0 += w[r][0] * a0;     // left partial of F[j]
            t2_3 += w[r][2] * a5;     // right partial of F[j+3]
        }
        const int fb = FIDX(j);       // contiguous 4 (j mod 8 in {0,4})
#pragma unroll
        for (int jj = 0; jj < 4; jj++) FS[hrow][fb + jj] = f[jj];
        if ((j & 7) == 0) ELS[hrow][j >> 3] = t0_0;
        else              ERS[hrow][j >> 3] = t2_3;   // (j&7)==4
    }
    __syncthreads();

    // ---- phase 3: one (slice, h) per thread ----
    const int sl   = t & 255;
    const int hrow = t >> 8;
    const int s  = half * 256 + sl;
    const size_t gm = (size_t)b * NSLICE + s;
    const size_t mtile = gm >> 7;
    const int row = (int)(gm & 127);
    char* base = (char*)g_A + (mtile * 16 + hp) * 16384 + (size_t)row * 128;

    const float* FSr = FS[hrow];
    const int fbase = 9 * sl;
#pragma unroll
    for (int c8 = 0; c8 < 4; c8++) {
        float v[8];
#pragma unroll
        for (int cc = 0; cc < 8; cc++) {
            const int c = c8 * 8 + cc;
            v[cc] = FSr[fbase + c + (c >> 3)];
        }
        if (c8 == 0) v[0] -= ELS[hrow][sl];
        if (c8 == 3) v[7] -= ERS[hrow][sl + 3];
        uint4 u;
        __half2* hpx = reinterpret_cast<__half2*>(&u);
#pragma unroll
        for (int i = 0; i < 4; i++)
            hpx[i] = __floats2half2_rn(fmaxf(v[2 * i], 0.0f),
                                       fmaxf(v[2 * i + 1], 0.0f));
        const int ch = hrow * 4 + c8;
        *reinterpret_cast<uint4*>(base + ((ch ^ (row & 7)) << 4)) = u;
    }
}

// ---------------------------------------------------------------------------
// Kernel 2 (round-7 verbatim): g_W tiled/pre-swizzled fp16 of lin_w^T.
// ---------------------------------------------------------------------------
__global__ void __launch_bounds__(256) prepw(const float* __restrict__ lw) {
    __shared__ float tl[32][33];
    const int tx = threadIdx.x & 31;
    const int ty = threadIdx.x >> 5;      // 0..7
    const int n0 = blockIdx.x * 32;
    const int k0 = blockIdx.y * 32;
#pragma unroll
    for (int i = 0; i < 4; i++)
        tl[ty + 8 * i][tx] = lw[(size_t)(k0 + ty + 8 * i) * NTOT + n0 + tx];
    __syncthreads();
    const int k = k0 + tx;
    const int kc = k >> 6, col = k & 63;
    const int ch = col >> 3, off = (col & 7) * 2;
#pragma unroll
    for (int i = 0; i < 4; i++) {
        const int n = n0 + ty + 8 * i;
        const int bxW = n >> 8, rowW = n & 255;
        char* p = (char*)g_W + ((size_t)(bxW * 16 + kc) * 256 + rowW) * 128 +
                  ((ch ^ (rowW & 7)) << 4) + off;
        *reinterpret_cast<__half*>(p) = __float2half_rn(tl[tx][ty + 8 * i]);
    }
}

// ---------------------------------------------------------------------------
// Kernel 3 (round-7 verbatim): fp16 GEMM, mma.sync m16n8k16 + ldmatrix,
// cp.async.bulk + mbarrier. CTA tile 128x256, BK=64 halves; 3-stage ring
// (48KB/stage = 144KB). 512 threads, warps 2x8, warp tile 64x32.
// ---------------------------------------------------------------------------
#define A_STAGE   16384
#define B_STAGE   32768
#define STAGE_SZ  (A_STAGE + B_STAGE)
#define GEMM_SMEM (3 * STAGE_SZ)          // 144 KB dynamic
#define KCHUNKS   16

__global__ void __launch_bounds__(512) gemm(const float* __restrict__ bias,
                                            float* __restrict__ out) {
    extern __shared__ __align__(1024) char dsm[];
    __shared__ __align__(16) uint64_t mbar[3];

    const int t    = threadIdx.x;
    const int lane = t & 31;
    const int warp = t >> 5;
    const int wm   = warp >> 3;     // 0..1
    const int wn   = warp & 7;      // 0..7
    const int bx   = blockIdx.x;    // N block (0..1)
    const int by   = blockIdx.y;    // M block (0..255)

    const uint32_t smem_base = smem_u32(dsm);
    uint32_t mb[3];
#pragma unroll
    for (int i = 0; i < 3; i++) mb[i] = smem_u32(&mbar[i]);

    const char* Abase = (const char*)g_A + (size_t)by * 16 * 16384;
    const char* Bbase = (const char*)g_W + (size_t)bx * 16 * 32768;

    if (t == 0) {
        MBARRIER_INIT(mb[0], 1);
        MBARRIER_INIT(mb[1], 1);
        MBARRIER_INIT(mb[2], 1);
        asm volatile("fence.proxy.async.shared::cta;" ::: "memory");
    }
    __syncthreads();

    auto issue = [&](int kc) {
        const int s = kc % 3;
        const uint32_t sa = smem_base + s * STAGE_SZ;
        MBARRIER_EXPECT_TX(mb[s], STAGE_SZ);
        bulk_g2s(sa,           Abase + (size_t)kc * A_STAGE, A_STAGE, mb[s]);
        bulk_g2s(sa + A_STAGE, Bbase + (size_t)kc * B_STAGE, B_STAGE, mb[s]);
    };

    if (t == 0) { issue(0); issue(1); issue(2); }

    float c[4][2][2][4];
#pragma unroll
    for (int i = 0; i < 4; i++)
#pragma unroll
        for (int j = 0; j < 2; j++)
#pragma unroll
            for (int k = 0; k < 2; k++)
#pragma unroll
                for (int l = 0; l < 4; l++) c[i][j][k][l] = 0.0f;

    // ldmatrix per-lane address components (within a stage)
    const int rm     = lane & 7;
    const int a_roff = (wm * 64 + (lane & 15)) * 128;                      // + mt*2048
    const int a_m    = lane >> 4;
    const int b_roff = (wn * 32 + ((lane >> 4) << 3) + (lane & 7)) * 128;  // + p*2048
    const int b_m    = (lane >> 3) & 1;

    for (int kc = 0; kc < KCHUNKS; kc++) {
        const int st = kc % 3;
        MBARRIER_WAIT_PARITY(mb[st], (kc / 3) & 1);

        const uint32_t sa = smem_base + st * STAGE_SZ;
        const uint32_t sb = sa + A_STAGE;

#pragma unroll
        for (int ks = 0; ks < 4; ks++) {                      // k16 steps
            uint32_t a[4][4], bf[2][4];
#pragma unroll
            for (int mt = 0; mt < 4; mt++)
                ldsm_x4(a[mt], sa + a_roff + mt * 2048 +
                               (((2 * ks + a_m) ^ rm) << 4));
#pragma unroll
            for (int p = 0; p < 2; p++)
                ldsm_x4(bf[p], sb + b_roff + p * 2048 +
                               (((2 * ks + b_m) ^ rm) << 4));
#pragma unroll
            for (int mt = 0; mt < 4; mt++)
#pragma unroll
                for (int p = 0; p < 2; p++) {
                    mma_f16(c[mt][p][0], a[mt], bf[p][0], bf[p][1]);
                    mma_f16(c[mt][p][1], a[mt], bf[p][2], bf[p][3]);
                }
        }

        __syncthreads();                    // all warps done reading stage st
        if (t == 0 && kc + 3 < KCHUNKS) issue(kc + 3);
    }

    // epilogue: += bias, write fp32
#pragma unroll
    for (int p = 0; p < 2; p++)
#pragma unroll
        for (int ns = 0; ns < 2; ns++) {
            const int col = bx * 256 + wn * 32 + p * 16 + ns * 8 + 2 * (lane & 3);
            const float b0 = bias[col], b1 = bias[col + 1];
#pragma unroll
            for (int mt = 0; mt < 4; mt++) {
                const int r0 = by * 128 + wm * 64 + mt * 16 + (lane >> 2);
                float2 v0 = make_float2(c[mt][p][ns][0] + b0, c[mt][p][ns][1] + b1);
                float2 v1 = make_float2(c[mt][p][ns][2] + b0, c[mt][p][ns][3] + b1);
                *reinterpret_cast<float2*>(&out[(size_t)r0 * NTOT + col])       = v0;
                *reinterpret_cast<float2*>(&out[(size_t)(r0 + 8) * NTOT + col]) = v1;
            }
        }
}

// ---------------------------------------------------------------------------
extern "C" void kernel_launch(void* const* d_in, const int* in_sizes, int n_in,
                              void* d_out, int out_size) {
    const float* images = (const float*)d_in[0];
    const float* conv_w = (const float*)d_in[1];
    const float* conv_b = (const float*)d_in[2];
    const float* lin_w  = (const float*)d_in[3];
    const float* lin_b  = (const float*)d_in[4];
    float* out = (float*)d_out;

    cudaFuncSetAttribute(gemm, cudaFuncAttributeMaxDynamicSharedMemorySize,
                         GEMM_SMEM);

    abuild<<<dim3(2, 16, IMG_B), 512>>>(images, conv_w, conv_b);
    prepw<<<dim3(NTOT / 32, KTOT / 32), 256>>>(lin_w);
    gemm<<<dim3(NTOT / 256, MTOT / 128), 512, GEMM_SMEM>>>(lin_b, out);
}

// round 11
// speedup vs baseline: 2.3399x; 1.0686x over previous
#include <cuda_runtime.h>
#include <cuda_fp16.h>
#include <cstdint>
#include <cstddef>

#define IMG_B   64
#define IMG_H   32
#define IMG_W   4096
#define NSLICE  512
#define MTOT    32768
#define KTOT    1024
#define NTOT    512

// Tiled + pre-swizzled operand storage.
//   g_A: [m_tile 0..255][kc 0..15][row 0..127][16B chunk, ch^(row&7)]  64 MB
//   g_W: [bx 0..1][kc 0..15][row 0..255][16B chunk, ch^(row&7)]        1 MB
__device__ __align__(128) __half g_A[(size_t)MTOT * KTOT];
__device__ __align__(128) __half g_W[(size_t)NTOT * KTOT];

// ---------------------------------------------------------------------------
// helpers
// ---------------------------------------------------------------------------
__device__ __forceinline__ uint32_t smem_u32(const void* p) {
    uint32_t a;
    asm("{ .reg .u64 t; cvta.to.shared.u64 t, %1; cvt.u32.u64 %0, t; }" : "=r"(a) : "l"(p));
    return a;
}

__device__ __forceinline__ void ldsm_x4(uint32_t r[4], uint32_t addr) {
    asm volatile("ldmatrix.sync.aligned.m8n8.x4.shared.b16 {%0,%1,%2,%3}, [%4];"
                 : "=r"(r[0]), "=r"(r[1]), "=r"(r[2]), "=r"(r[3]) : "r"(addr));
}

__device__ __forceinline__ void mma_f16(float c[4], const uint32_t a[4],
                                        uint32_t b0, uint32_t b1) {
    asm volatile(
        "mma.sync.aligned.m16n8k16.row.col.f32.f16.f16.f32 "
        "{%0,%1,%2,%3}, {%4,%5,%6,%7}, {%8,%9}, {%0,%1,%2,%3};"
        : "+f"(c[0]), "+f"(c[1]), "+f"(c[2]), "+f"(c[3])
        : "r"(a[0]), "r"(a[1]), "r"(a[2]), "r"(a[3]), "r"(b0), "r"(b1));
}

__device__ __forceinline__ void bulk_g2s(uint32_t sdst, const void* gsrc,
                                         uint32_t bytes, uint32_t mbar) {
    asm volatile(
        "cp.async.bulk.shared::cluster.global.mbarrier::complete_tx::bytes "
        "[%0], [%1], %2, [%3];"
        :: "r"(sdst), "l"(gsrc), "r"(bytes), "r"(mbar) : "memory");
}

#define MBARRIER_INIT(a, c) \
    asm volatile("mbarrier.init.shared.b64 [%0], %1;" :: "r"((uint32_t)(a)), "r"((uint32_t)(c)) : "memory")
#define MBARRIER_EXPECT_TX(a, b) \
    asm volatile("mbarrier.arrive.expect_tx.shared.b64 _, [%0], %1;" :: "r"((uint32_t)(a)), "r"((uint32_t)(b)) : "memory")

#define MBARRIER_WAIT_PARITY(mbar_addr, parity) do { \
    uint32_t _mbar = (uint32_t)(mbar_addr); \
    uint32_t _par  = (uint32_t)(parity); \
    uint32_t _done_; \
    asm volatile("{\n\t.reg .pred p;\n\t" \
        "mbarrier.try_wait.parity.acquire.cta.shared::cta.b64 p, [%1], %2;\n\t" \
        "selp.b32 %0, 1, 0, p;\n\t}" \
        : "=r"(_done_) : "r"(_mbar), "r"(_par) : "memory"); \
    if (!_done_) { \
        asm volatile("{\n\t.reg .pred P1;\n\t" \
            "WAIT_LOOP_%=:\n\t" \
            "mbarrier.try_wait.parity.acquire.cta.shared::cta.b64 P1, [%0], %1, 0x989680;\n\t" \
            "@P1 bra.uni WAIT_DONE_%=;\n\t" \
            "bra.uni WAIT_LOOP_%=;\n\t" \
            "WAIT_DONE_%=:\n\t}" \
            :: "r"(_mbar), "r"(_par) : "memory"); \
    } \
} while (0)

// ---------------------------------------------------------------------------
// Kernel 1 (abuild v3, round-10 verbatim): 2 h-rows per block, 512 threads.
// Grid (2 halves, 16 h-pairs, 64 b).
// ---------------------------------------------------------------------------
#define SPAN    2088            // padded strip length (522 float4)
#define NGRP    519             // groups of 4 F outputs per h row
#define FSSZ    2336            // >= FIDX(2075)+1
#define FIDX(j) ((j) + ((j) >> 3))

__global__ void __launch_bounds__(512) abuild(const float* __restrict__ img,
                                              const float* __restrict__ cw,
                                              const float* __restrict__ cb) {
    __shared__ float PS[4][SPAN];
    __shared__ float FS[2][FSSZ];
    __shared__ float ELS[2][260], ERS[2][260];

    const int half = blockIdx.x;
    const int hp   = blockIdx.y;         // h pair: rows 2hp, 2hp+1
    const int b    = blockIdx.z;
    const int t    = threadIdx.x;

    const int O = half * 2048;           // strip: g = O - 16 + 4*pi4

    float w[3][3];
#pragma unroll
    for (int i = 0; i < 3; i++)
#pragma unroll
        for (int j = 0; j < 3; j++) w[i][j] = cw[i * 3 + j];
    const float bias = cb[0];

    // interior float4 range [lo4, hi4] (outside: all-1.0 pad or zero row)
    const int lo4 = (half == 0) ? 4 : 0;
    const int hi4 = (half == 0) ? 521 : 515;

    // ---- phase 1: 4 rows x 522 float4 tasks ----
    for (int idx = t; idx < 4 * 522; idx += 512) {
        const int r   = idx / 522;
        const int pi4 = idx - r * 522;
        const int inrow = 2 * hp + r - 1;
        float4 v;
        if ((unsigned)inrow >= 32u) {
            v = make_float4(0.f, 0.f, 0.f, 0.f);
        } else if (pi4 >= lo4 && pi4 <= hi4) {
            const float* rp = img + ((size_t)b * IMG_H + inrow) * IMG_W;
            v = *reinterpret_cast<const float4*>(rp + (O - 16 + pi4 * 4));
        } else {
            v = make_float4(1.f, 1.f, 1.f, 1.f);
        }
        *reinterpret_cast<float4*>(&PS[r][pi4 * 4]) = v;
    }
    __syncthreads();

    // ---- phase 2: F rows + edge partials; 4 outputs per task ----
    for (int idx = t; idx < 2 * NGRP; idx += 512) {
        const int hrow = idx / NGRP;
        const int grp  = idx - hrow * NGRP;
        const int j    = grp * 4;

        float s3[3], s8[3];
        float4 q1[3];
#pragma unroll
        for (int r = 0; r < 3; r++) {
            const float* pr = PS[hrow + r];
            s3[r] = pr[j + 3];
            q1[r] = *reinterpret_cast<const float4*>(pr + j + 4);
            s8[r] = pr[j + 8];
        }
        float f[4], t0_0 = 0.f, t2_3 = 0.f;
#pragma unroll
        for (int jj = 0; jj < 4; jj++) f[jj] = bias;
#pragma unroll
        for (int r = 0; r < 3; r++) {
            const float a0 = s3[r], a1 = q1[r].x, a2 = q1[r].y,
                        a3 = q1[r].z, a4 = q1[r].w, a5 = s8[r];
            f[0] += w[r][0] * a0 + w[r][1] * a1 + w[r][2] * a2;
            f[1] += w[r][0] * a1 + w[r][1] * a2 + w[r][2] * a3;
            f[2] += w[r][0] * a2 + w[r][1] * a3 + w[r][2] * a4;
            f[3] += w[r][0] * a3 + w[r][1] * a4 + w[r][2] * a5;
            t0_0 += w[r][0] * a0;     // left partial of F[j]
            t2_3 += w[r][2] * a5;     // right partial of F[j+3]
        }
        const int fb = FIDX(j);       // contiguous 4 (j mod 8 in {0,4})
#pragma unroll
        for (int jj = 0; jj < 4; jj++) FS[hrow][fb + jj] = f[jj];
        if ((j & 7) == 0) ELS[hrow][j >> 3] = t0_0;
        else              ERS[hrow][j >> 3] = t2_3;   // (j&7)==4
    }
    __syncthreads();

    // ---- phase 3: one (slice, h) per thread ----
    const int sl   = t & 255;
    const int hrow = t >> 8;
    const int s  = half * 256 + sl;
    const size_t gm = (size_t)b * NSLICE + s;
    const size_t mtile = gm >> 7;
    const int row = (int)(gm & 127);
    char* base = (char*)g_A + (mtile * 16 + hp) * 16384 + (size_t)row * 128;

    const float* FSr = FS[hrow];
    const int fbase = 9 * sl;
#pragma unroll
    for (int c8 = 0; c8 < 4; c8++) {
        float v[8];
#pragma unroll
        for (int cc = 0; cc < 8; cc++) {
            const int c = c8 * 8 + cc;
            v[cc] = FSr[fbase + c + (c >> 3)];
        }
        if (c8 == 0) v[0] -= ELS[hrow][sl];
        if (c8 == 3) v[7] -= ERS[hrow][sl + 3];
        uint4 u;
        __half2* hpx = reinterpret_cast<__half2*>(&u);
#pragma unroll
        for (int i = 0; i < 4; i++)
            hpx[i] = __floats2half2_rn(fmaxf(v[2 * i], 0.0f),
                                       fmaxf(v[2 * i + 1], 0.0f));
        const int ch = hrow * 4 + c8;
        *reinterpret_cast<uint4*>(base + ((ch ^ (row & 7)) << 4)) = u;
    }
}

// ---------------------------------------------------------------------------
// Kernel 2 (round-10 verbatim): g_W tiled/pre-swizzled fp16 of lin_w^T.
// ---------------------------------------------------------------------------
__global__ void __launch_bounds__(256) prepw(const float* __restrict__ lw) {
    __shared__ float tl[32][33];
    const int tx = threadIdx.x & 31;
    const int ty = threadIdx.x >> 5;      // 0..7
    const int n0 = blockIdx.x * 32;
    const int k0 = blockIdx.y * 32;
#pragma unroll
    for (int i = 0; i < 4; i++)
        tl[ty + 8 * i][tx] = lw[(size_t)(k0 + ty + 8 * i) * NTOT + n0 + tx];
    __syncthreads();
    const int k = k0 + tx;
    const int kc = k >> 6, col = k & 63;
    const int ch = col >> 3, off = (col & 7) * 2;
#pragma unroll
    for (int i = 0; i < 4; i++) {
        const int n = n0 + ty + 8 * i;
        const int bxW = n >> 8, rowW = n & 255;
        char* p = (char*)g_W + ((size_t)(bxW * 16 + kc) * 256 + rowW) * 128 +
                  ((ch ^ (rowW & 7)) << 4) + off;
        *reinterpret_cast<__half*>(p) = __float2half_rn(tl[tx][ty + 8 * i]);
    }
}

// ---------------------------------------------------------------------------
// Kernel 3: fp16 GEMM, mma.sync m16n8k16 + ldmatrix, cp.async.bulk + mbarrier.
// CTA tile 128x256, BK=64 halves; ***4-stage*** ring (48KB/stage = 192KB).
// 512 threads, warps 2x8, warp tile 64x32. Only change vs round 10: ring depth
// 3 -> 4 so the copy of chunk kc+4 has 3 chunk-times of slack instead of 2.
// ---------------------------------------------------------------------------
#define A_STAGE   16384
#define B_STAGE   32768
#define STAGE_SZ  (A_STAGE + B_STAGE)
#define NSTAGE    4
#define GEMM_SMEM (NSTAGE * STAGE_SZ)     // 192 KB dynamic
#define KCHUNKS   16

__global__ void __launch_bounds__(512) gemm(const float* __restrict__ bias,
                                            float* __restrict__ out) {
    extern __shared__ __align__(1024) char dsm[];
    __shared__ __align__(16) uint64_t mbar[NSTAGE];

    const int t    = threadIdx.x;
    const int lane = t & 31;
    const int warp = t >> 5;
    const int wm   = warp >> 3;     // 0..1
    const int wn   = warp & 7;      // 0..7
    const int bx   = blockIdx.x;    // N block (0..1)
    const int by   = blockIdx.y;    // M block (0..255)

    const uint32_t smem_base = smem_u32(dsm);
    uint32_t mb[NSTAGE];
#pragma unroll
    for (int i = 0; i < NSTAGE; i++) mb[i] = smem_u32(&mbar[i]);

    const char* Abase = (const char*)g_A + (size_t)by * 16 * 16384;
    const char* Bbase = (const char*)g_W + (size_t)bx * 16 * 32768;

    if (t == 0) {
#pragma unroll
        for (int i = 0; i < NSTAGE; i++) MBARRIER_INIT(mb[i], 1);
        asm volatile("fence.proxy.async.shared::cta;" ::: "memory");
    }
    __syncthreads();

    auto issue = [&](int kc) {
        const int s = kc & (NSTAGE - 1);
        const uint32_t sa = smem_base + s * STAGE_SZ;
        MBARRIER_EXPECT_TX(mb[s], STAGE_SZ);
        bulk_g2s(sa,           Abase + (size_t)kc * A_STAGE, A_STAGE, mb[s]);
        bulk_g2s(sa + A_STAGE, Bbase + (size_t)kc * B_STAGE, B_STAGE, mb[s]);
    };

    if (t == 0) { issue(0); issue(1); issue(2); issue(3); }

    float c[4][2][2][4];
#pragma unroll
    for (int i = 0; i < 4; i++)
#pragma unroll
        for (int j = 0; j < 2; j++)
#pragma unroll
            for (int k = 0; k < 2; k++)
#pragma unroll
                for (int l = 0; l < 4; l++) c[i][j][k][l] = 0.0f;

    // ldmatrix per-lane address components (within a stage)
    const int rm     = lane & 7;
    const int a_roff = (wm * 64 + (lane & 15)) * 128;                      // + mt*2048
    const int a_m    = lane >> 4;
    const int b_roff = (wn * 32 + ((lane >> 4) << 3) + (lane & 7)) * 128;  // + p*2048
    const int b_m    = (lane >> 3) & 1;

    for (int kc = 0; kc < KCHUNKS; kc++) {
        const int st = kc & (NSTAGE - 1);
        MBARRIER_WAIT_PARITY(mb[st], (kc >> 2) & 1);

        const uint32_t sa = smem_base + st * STAGE_SZ;
        const uint32_t sb = sa + A_STAGE;

#pragma unroll
        for (int ks = 0; ks < 4; ks++) {                      // k16 steps
            uint32_t a[4][4], bf[2][4];
#pragma unroll
            for (int mt = 0; mt < 4; mt++)
                ldsm_x4(a[mt], sa + a_roff + mt * 2048 +
                               (((2 * ks + a_m) ^ rm) << 4));
#pragma unroll
            for (int p = 0; p < 2; p++)
                ldsm_x4(bf[p], sb + b_roff + p * 2048 +
                               (((2 * ks + b_m) ^ rm) << 4));
#pragma unroll
            for (int mt = 0; mt < 4; mt++)
#pragma unroll
                for (int p = 0; p < 2; p++) {
                    mma_f16(c[mt][p][0], a[mt], bf[p][0], bf[p][1]);
                    mma_f16(c[mt][p][1], a[mt], bf[p][2], bf[p][3]);
                }
        }

        __syncthreads();                    // all warps done reading stage st
        if (t == 0 && kc + NSTAGE < KCHUNKS) issue(kc + NSTAGE);
    }

    // epilogue: += bias, write fp32
#pragma unroll
    for (int p = 0; p < 2; p++)
#pragma unroll
        for (int ns = 0; ns < 2; ns++) {
            const int col = bx * 256 + wn * 32 + p * 16 + ns * 8 + 2 * (lane & 3);
            const float b0 = bias[col], b1 = bias[col + 1];
#pragma unroll
            for (int mt = 0; mt < 4; mt++) {
                const int r0 = by * 128 + wm * 64 + mt * 16 + (lane >> 2);
                float2 v0 = make_float2(c[mt][p][ns][0] + b0, c[mt][p][ns][1] + b1);
                float2 v1 = make_float2(c[mt][p][ns][2] + b0, c[mt][p][ns][3] + b1);
                *reinterpret_cast<float2*>(&out[(size_t)r0 * NTOT + col])       = v0;
                *reinterpret_cast<float2*>(&out[(size_t)(r0 + 8) * NTOT + col]) = v1;
            }
        }
}

// ---------------------------------------------------------------------------
extern "C" void kernel_launch(void* const* d_in, const int* in_sizes, int n_in,
                              void* d_out, int out_size) {
    const float* images = (const float*)d_in[0];
    const float* conv_w = (const float*)d_in[1];
    const float* conv_b = (const float*)d_in[2];
    const float* lin_w  = (const float*)d_in[3];
    const float* lin_b  = (const float*)d_in[4];
    float* out = (float*)d_out;

    cudaFuncSetAttribute(gemm, cudaFuncAttributeMaxDynamicSharedMemorySize,
                         GEMM_SMEM);

    abuild<<<dim3(2, 16, IMG_B), 512>>>(images, conv_w, conv_b);
    prepw<<<dim3(NTOT / 32, KTOT / 32), 256>>>(lin_w);
    gemm<<<dim3(NTOT / 256, MTOT / 128), 512, GEMM_SMEM>>>(lin_b, out);
}